// round 16
// baseline (speedup 1.0000x reference)
#include <cuda_runtime.h>
#include <cuda_fp16.h>
#include <math.h>
#include <stddef.h>
#include <stdint.h>

#define B_   2
#define L_   2048
#define D_   1024
#define H_   16
#define HD   64
#define LNEG 10000.0f
#define LOG2E 1.4426950408889634f

// ---------------- device scratch ----------------
__device__ __half g_h   [8388608];                        // x | W_in | W_out (fp16)
__device__ __half g_qkvh[(size_t)3 * B_ * H_ * L_ * HD];  // q,k,v [part][b][h][l][d]
__device__ __half g_aoh [(size_t)B_ * L_ * D_];           // attn out [b][l][D]
__device__ float  g_maskf[B_ * L_];                       // LNEG*LOG2E*pad
#define XH  0
#define WIH 4194304
#define WOH 7340032
#define N4X  1048576   // float4 counts
#define N4WI 786432
#define N4WO 262144

// ---------------- helpers ----------------
__device__ __forceinline__ float ex2(float x) {
    float y; asm("ex2.approx.f32 %0, %1;" : "=f"(y) : "f"(x)); return y;
}
__device__ __forceinline__ void mma_f16(float* d, const uint32_t* a,
                                        uint32_t b0, uint32_t b1, const float* c) {
    asm("mma.sync.aligned.m16n8k16.row.col.f32.f16.f16.f32 "
        "{%0,%1,%2,%3},{%4,%5,%6,%7},{%8,%9},{%10,%11,%12,%13};"
        : "=f"(d[0]), "=f"(d[1]), "=f"(d[2]), "=f"(d[3])
        : "r"(a[0]), "r"(a[1]), "r"(a[2]), "r"(a[3]),
          "r"(b0), "r"(b1),
          "f"(c[0]), "f"(c[1]), "f"(c[2]), "f"(c[3]));
}
__device__ __forceinline__ void ldsm4(uint32_t* r, uint32_t a) {
    asm volatile("ldmatrix.sync.aligned.m8n8.x4.shared.b16 {%0,%1,%2,%3}, [%4];"
        : "=r"(r[0]), "=r"(r[1]), "=r"(r[2]), "=r"(r[3]) : "r"(a));
}
__device__ __forceinline__ void ldsm4t(uint32_t* r, uint32_t a) {
    asm volatile("ldmatrix.sync.aligned.m8n8.x4.trans.shared.b16 {%0,%1,%2,%3}, [%4];"
        : "=r"(r[0]), "=r"(r[1]), "=r"(r[2]), "=r"(r[3]) : "r"(a));
}
__device__ __forceinline__ uint32_t smem_u32(const void* p) {
    uint32_t a;
    asm("{ .reg .u64 t; cvta.to.shared.u64 t, %1; cvt.u32.u64 %0, t; }" : "=r"(a) : "l"(p));
    return a;
}
__device__ __forceinline__ void cpa16(uint32_t dst_smem, const void* src) {
    asm volatile("cp.async.ca.shared.global [%0], [%1], 16;" :: "r"(dst_smem), "l"(src));
}
__device__ __forceinline__ void cpa_commit() { asm volatile("cp.async.commit_group;"); }
template<int N> __device__ __forceinline__ void cpa_wait() {
    asm volatile("cp.async.wait_group %0;" :: "n"(N));
}

// fp16 tile: rows of 128B (64 halfs), 8 chunks of 16B, chunk c of row r at c^(r&7)
#define TOFF(row, ch) (((row) << 7) + (((ch) ^ ((row) & 7)) << 4))

// ---------------- fp16 pre-conversion: all three tensors in one launch --------------
__global__ void cvt_all(const float4* __restrict__ x,
                        const float4* __restrict__ wi,
                        const float4* __restrict__ wo)
{
    const int total = N4X + N4WI + N4WO;
    for (int i = blockIdx.x * blockDim.x + threadIdx.x; i < total;
         i += gridDim.x * blockDim.x) {
        const float4* src; int j; int off;
        if (i < N4X)              { src = x;  j = i;               off = XH; }
        else if (i < N4X + N4WI)  { src = wi; j = i - N4X;         off = WIH; }
        else                      { src = wo; j = i - N4X - N4WI;  off = WOH; }
        float4 v = src[j];
        __half2* out = (__half2*)(g_h + off);
        out[2 * j]     = __floats2half2_rn(v.x, v.y);
        out[2 * j + 1] = __floats2half2_rn(v.z, v.w);
    }
}

// ---------------- mask dtype detection + float materialization ----------------
__global__ void mask_prep(const void* __restrict__ raw, int n)
{
    __shared__ int notint, notfloat;
    if (threadIdx.x == 0) { notint = 0; notfloat = 0; }
    __syncthreads();
    const unsigned* w = (const unsigned*)raw;
    const float*    f = (const float*)raw;
    int nw = n >> 2;
    for (int i = threadIdx.x; i < nw; i += blockDim.x) {
        unsigned x = w[i];
        if (x > 1u) notint = 1;
        float xf = f[i];
        if (xf != 0.0f && xf != 1.0f) notfloat = 1;
    }
    __syncthreads();
    const float MV = LNEG * LOG2E;
    if (!notint) {
        const int* wi = (const int*)raw;
        for (int i = threadIdx.x; i < n; i += blockDim.x)
            g_maskf[i] = wi[i] ? MV : 0.0f;
    } else if (!notfloat) {
        for (int i = threadIdx.x; i < n; i += blockDim.x)
            g_maskf[i] = (f[i] != 0.0f) ? MV : 0.0f;
    } else {
        const unsigned char* c = (const unsigned char*)raw;
        for (int i = threadIdx.x; i < n; i += blockDim.x)
            g_maskf[i] = c[i] ? MV : 0.0f;
    }
}

// ---------------- fp16 NT GEMM: 128x128 tile, k-slab 64, 3-stage cp.async -----------
// MODE 1: A = x (g_h+XH), B = W_in (g_h+WIH) -> scatter q/k/v fp16 [part][b][h][l][d]
// MODE 0: A = g_aoh,      B = W_out (g_h+WOH) -> C row-major fp32 (+bias)
#define STG 3
template<int MODE>
__global__ __launch_bounds__(256, 2) void hgemm(
    const float* __restrict__ bias, float* __restrict__ C, int N)
{
    extern __shared__ char smem[];
    const uint32_t sb = smem_u32(smem);

    const int tid = threadIdx.x;
    const int lane = tid & 31, wid = tid >> 5;
    const int gid = lane >> 2, tig = lane & 3;
    const int sub = lane >> 3, lr = lane & 7;
    const int subhi = sub >> 1, sublo = sub & 1;
    const int wm = wid & 1, wn = wid >> 1;
    const int m0 = blockIdx.y * 128, n0 = blockIdx.x * 128;

    const __half* Ap = (MODE == 0) ? g_aoh : (g_h + XH);
    const __half* Bw = (MODE == 0) ? (g_h + WOH) : (g_h + WIH);
    const int K = D_;

    float acc[4][4][4];
    #pragma unroll
    for (int mt = 0; mt < 4; mt++)
        #pragma unroll
        for (int nt = 0; nt < 4; nt++)
            #pragma unroll
            for (int c = 0; c < 4; c++) acc[mt][nt][c] = 0.0f;

    auto stage = [&](int t, int s) {
        uint32_t base = sb + s * 32768;
        #pragma unroll
        for (int p = 0; p < 8; p++) {
            int idx = tid + 256 * p;
            int mat = idx >> 10;
            int rc  = idx & 1023;
            int row = rc >> 3, ch = rc & 7;
            const __half* src = (mat ? Bw + (size_t)(n0 + row) * K
                                     : Ap + (size_t)(m0 + row) * K) + t * 64 + ch * 8;
            cpa16(base + mat * 16384 + TOFF(row, ch), src);
        }
        cpa_commit();
    };

    stage(0, 0);
    stage(1, 1);
    stage(2, 2);

    const int T = K / 64;
    for (int t = 0; t < T; t++) {
        cpa_wait<STG - 1>();
        __syncthreads();
        uint32_t Ab = sb + (t % STG) * 32768;
        uint32_t Bb = Ab + 16384;

        #pragma unroll
        for (int kk = 0; kk < 4; kk++) {
            int ch = 2 * kk + subhi;
            uint32_t afr[4][4], bfr[2][4];
            #pragma unroll
            for (int mt = 0; mt < 4; mt++) {
                int row = wm * 64 + mt * 16 + sublo * 8 + lr;
                ldsm4(afr[mt], Ab + ((row << 7) + ((ch ^ lr) << 4)));
            }
            #pragma unroll
            for (int ng = 0; ng < 2; ng++) {
                int row = wn * 32 + ng * 16 + sublo * 8 + lr;
                ldsm4(bfr[ng], Bb + ((row << 7) + ((ch ^ lr) << 4)));
            }
            #pragma unroll
            for (int mt = 0; mt < 4; mt++)
                #pragma unroll
                for (int nt = 0; nt < 4; nt++)
                    mma_f16(acc[mt][nt], afr[mt],
                            bfr[nt >> 1][nt & 1], bfr[nt >> 1][(nt & 1) + 2],
                            acc[mt][nt]);
        }
        __syncthreads();
        if (t + STG < T) stage(t + STG, (t + STG) % STG);
    }

    #pragma unroll
    for (int mt = 0; mt < 4; mt++) {
        #pragma unroll
        for (int hh = 0; hh < 2; hh++) {
            int m = m0 + wm * 64 + mt * 16 + gid + hh * 8;
            #pragma unroll
            for (int nt = 0; nt < 4; nt++) {
                int n = n0 + wn * 32 + nt * 8 + 2 * tig;
                float vx = acc[mt][nt][2 * hh]     + bias[n];
                float vy = acc[mt][nt][2 * hh + 1] + bias[n + 1];
                if (MODE == 0) {
                    float2 val = { vx, vy };
                    *(float2*)&C[(size_t)m * N + n] = val;
                } else {
                    int part = n >> 10;
                    int col  = n & 1023;
                    int hd   = col >> 6;
                    int dd   = col & 63;
                    int bb   = m >> 11;
                    int ll   = m & 2047;
                    *(__half2*)&g_qkvh[((((size_t)part * B_ + bb) * H_ + hd) * L_ + ll) * HD + dd] =
                        __floats2half2_rn(vx, vy);
                }
            }
        }
    }
}

// ---------------- flash attention: bias direct-to-register, fused softmax+PV --------
// 128 threads = 4 warps; warp w owns q rows [w*16, w*16+16).
// smem: K/V buf0 16KB | K/V buf1 16KB | Q 8KB = 40KB -> occ 4
__global__ __launch_bounds__(128, 4) void flash_h(const float* __restrict__ attn_bias)
{
    extern __shared__ char smf[];
    const uint32_t sb = smem_u32(smf);      // K/V bufs: s*16384 (K +0, V +8192)
    const uint32_t sQ = sb + 32768;         // Q: 64 rows x 128B

    const int tid = threadIdx.x;
    const int lane = tid & 31, w = tid >> 5;
    const int gid = lane >> 2, tig = lane & 3;
    const int sub = lane >> 3, lr = lane & 7;
    const int subhi = sub >> 1, sublo = sub & 1;
    const int b = blockIdx.z, h = blockIdx.y, q0 = blockIdx.x * 64;

    const __half* Qg = g_qkvh + (((size_t)(0 * B_ + b) * H_ + h) * L_ + q0) * HD;
    const __half* Kg = g_qkvh + (((size_t)(1 * B_ + b) * H_ + h) * L_) * HD;
    const __half* Vg = g_qkvh + (((size_t)(2 * B_ + b) * H_ + h) * L_) * HD;
    const float* biasbase = attn_bias + (((size_t)b * H_ + h) * L_ + q0) * L_;
    const float* mkb = g_maskf + b * L_;

    // K/V stager (all threads): 2 mats x 64 rows x 8 chunks = 1024 over 128 threads
    auto stageA = [&](int t, int s) {
        uint32_t base = sb + s * 16384;
        #pragma unroll
        for (int p = 0; p < 8; p++) {
            int idx = tid + 128 * p;
            int mat = idx >> 9;
            int rc  = idx & 511;
            int row = rc >> 3, ch = rc & 7;
            const __half* src = (mat ? Vg : Kg) + (size_t)(t * 64 + row) * HD + ch * 8;
            cpa16(base + mat * 8192 + TOFF(row, ch), src);
        }
        cpa_commit();
    };

    // stage Q, pull persistent A-fragments
    #pragma unroll
    for (int p = 0; p < 4; p++) {
        int idx = tid + 128 * p;
        int row = idx >> 3, ch = idx & 7;
        cpa16(sQ + TOFF(row, ch), Qg + row * HD + ch * 8);
    }
    cpa_commit(); cpa_wait<0>();
    __syncthreads();

    uint32_t aq[4][4];
    {
        int row = w * 16 + sublo * 8 + lr;
        #pragma unroll
        for (int kk = 0; kk < 4; kk++)
            ldsm4(aq[kk], sQ + ((row << 7) + (((2 * kk + subhi) ^ lr) << 4)));
    }

    float o[8][4];
    #pragma unroll
    for (int nt = 0; nt < 8; nt++)
        #pragma unroll
        for (int c = 0; c < 4; c++) o[nt][c] = 0.0f;
    float den[2] = { 0.0f, 0.0f };

    const float SC = 0.125f * LOG2E;

    stageA(0, 0);

    const int T = L_ / 64;   // 32 key tiles
    for (int t = 0; t < T; t++) {
        const int k0 = t * 64;
        __syncthreads();               // all warps done reading buf (t+1)&1 (tile t-1)
        if (t + 1 < T) { stageA(t + 1, (t + 1) & 1); }

        // bias for tile t -> registers, issued NOW (consumed after S-mma: LDG latency
        // hides under the mma block). Fragment layout: bb[hh][nt] = float2 at
        // (row w*16+gid+8hh, keys k0+8nt+2tig).
        float2 bb[2][8];
        #pragma unroll
        for (int hh = 0; hh < 2; hh++) {
            const float* bp = biasbase + (size_t)(w * 16 + gid + 8 * hh) * L_ + k0 + 2 * tig;
            #pragma unroll
            for (int nt = 0; nt < 8; nt++)
                bb[hh][nt] = *(const float2*)(bp + nt * 8);
        }

        if (t + 1 < T) cpa_wait<1>(); else cpa_wait<0>();   // K/V tile t done
        __syncthreads();               // visible to all warps
        const uint32_t sK = sb + (t & 1) * 16384;
        const uint32_t sV = sK + 8192;

        // S = Q K^T
        float s[8][4];
        #pragma unroll
        for (int nt = 0; nt < 8; nt++)
            #pragma unroll
            for (int c = 0; c < 4; c++) s[nt][c] = 0.0f;
        #pragma unroll
        for (int kk = 0; kk < 4; kk++) {
            int ch = 2 * kk + subhi;
            uint32_t bfr[4][4];
            #pragma unroll
            for (int ng = 0; ng < 4; ng++) {
                int row = ng * 16 + sublo * 8 + lr;
                ldsm4(bfr[ng], sK + ((row << 7) + ((ch ^ lr) << 4)));
            }
            #pragma unroll
            for (int nt = 0; nt < 8; nt++)
                mma_f16(s[nt], aq[kk],
                        bfr[nt >> 1][nt & 1], bfr[nt >> 1][(nt & 1) + 2],
                        s[nt]);
        }

        // fold bias+mask into s (mask L2-hot, loaded here)
        #pragma unroll
        for (int nt = 0; nt < 8; nt++) {
            float2 mk = *(const float2*)(mkb + k0 + nt * 8 + 2 * tig);
            #pragma unroll
            for (int hh = 0; hh < 2; hh++) {
                s[nt][2 * hh]     = fmaf(s[nt][2 * hh],     SC, fmaf(bb[hh][nt].x, LOG2E, -mk.x));
                s[nt][2 * hh + 1] = fmaf(s[nt][2 * hh + 1], SC, fmaf(bb[hh][nt].y, LOG2E, -mk.y));
            }
        }

        // fused softmax + PV per k-slice: exp just nt=2kk,2kk+1, then 8 PV mma
        #pragma unroll
        for (int kk = 0; kk < 4; kk++) {
            uint32_t vf[4][4];
            #pragma unroll
            for (int ng = 0; ng < 4; ng++) {
                int row = kk * 16 + sublo * 8 + lr;
                int ch  = 2 * ng + subhi;
                ldsm4t(vf[ng], sV + ((row << 7) + ((ch ^ lr) << 4)));
            }
            uint32_t pa[4];
            #pragma unroll
            for (int half = 0; half < 2; half++) {
                int nt = 2 * kk + half;
                #pragma unroll
                for (int hh = 0; hh < 2; hh++) {
                    float p0 = ex2(s[nt][2 * hh]);
                    float p1 = ex2(s[nt][2 * hh + 1]);
                    den[hh] += p0 + p1;
                    __half2 hp = __floats2half2_rn(p0, p1);
                    pa[hh + 2 * half] = *(uint32_t*)&hp;
                }
            }
            #pragma unroll
            for (int nt = 0; nt < 8; nt++)
                mma_f16(o[nt], pa,
                        vf[nt >> 1][(nt & 1) * 2], vf[nt >> 1][(nt & 1) * 2 + 1],
                        o[nt]);
        }
    }

    // reduce den within lane-quad
    #pragma unroll
    for (int hh = 0; hh < 2; hh++) {
        den[hh] += __shfl_xor_sync(0xffffffffu, den[hh], 1);
        den[hh] += __shfl_xor_sync(0xffffffffu, den[hh], 2);
    }

    // normalize + write fp16 attn-out (feeds MODE0 GEMM)
    #pragma unroll
    for (int hh = 0; hh < 2; hh++) {
        float inv = 1.0f / den[hh];
        int l = q0 + w * 16 + gid + 8 * hh;
        #pragma unroll
        for (int nt = 0; nt < 8; nt++) {
            *(__half2*)&g_aoh[((size_t)b * L_ + l) * D_ + h * HD + nt * 8 + 2 * tig] =
                __floats2half2_rn(o[nt][2 * hh] * inv, o[nt][2 * hh + 1] * inv);
        }
    }
}

// ---------------- launch ----------------
extern "C" void kernel_launch(void* const* d_in, const int* in_sizes, int n_in,
                              void* d_out, int out_size)
{
    const float* x      = (const float*)d_in[0];
    const void*  mask   = d_in[1];
    const float* attn_b = (const float*)d_in[2];
    const float* b_in   = (const float*)d_in[4];
    const float* b_out  = (const float*)d_in[6];
    float*       out    = (float*)d_out;

    (void)in_sizes; (void)n_in; (void)out_size;

    mask_prep<<<1, 256>>>(mask, B_ * L_);
    cvt_all<<<1480, 256>>>((const float4*)x, (const float4*)d_in[3], (const float4*)d_in[5]);

    int gsmem = STG * 32768;   // 98,304 B
    cudaFuncSetAttribute(hgemm<1>, cudaFuncAttributeMaxDynamicSharedMemorySize, gsmem);
    cudaFuncSetAttribute(hgemm<0>, cudaFuncAttributeMaxDynamicSharedMemorySize, gsmem);

    // QKV projection -> q/k/v fp16
    hgemm<1><<<dim3((3 * D_) / 128, (B_ * L_) / 128), 256, gsmem>>>(
        b_in, nullptr, 3 * D_);

    int fsmem = 40960;   // 40 KB -> 4 CTAs/SM
    cudaFuncSetAttribute(flash_h, cudaFuncAttributeMaxDynamicSharedMemorySize, fsmem);
    flash_h<<<dim3(L_ / 64, H_, B_), 128, fsmem>>>(attn_b);

    // Output projection -> fp32 out
    hgemm<0><<<dim3(D_ / 128, (B_ * L_) / 128), 256, gsmem>>>(
        b_out, out, D_);
}

// round 17
// speedup vs baseline: 1.3332x; 1.3332x over previous
#include <cuda_runtime.h>
#include <cuda_fp16.h>
#include <math.h>
#include <stddef.h>
#include <stdint.h>

#define B_   2
#define L_   2048
#define D_   1024
#define H_   16
#define HD   64
#define LNEG 10000.0f
#define LOG2E 1.4426950408889634f

// ---------------- device scratch ----------------
__device__ __half g_h   [8388608];                        // x | W_in | W_out (fp16)
__device__ __half g_qkvh[(size_t)3 * B_ * H_ * L_ * HD];  // q,k,v [part][b][h][l][d]
__device__ __half g_aoh [(size_t)B_ * L_ * D_];           // attn out [b][l][D]
__device__ float  g_maskf[B_ * L_];                       // LNEG*LOG2E*pad
#define XH  0
#define WIH 4194304
#define WOH 7340032
#define N4X  1048576   // float4 counts
#define N4WI 786432
#define N4WO 262144

// ---------------- helpers ----------------
__device__ __forceinline__ float ex2(float x) {
    float y; asm("ex2.approx.f32 %0, %1;" : "=f"(y) : "f"(x)); return y;
}
__device__ __forceinline__ void mma_f16(float* d, const uint32_t* a,
                                        uint32_t b0, uint32_t b1, const float* c) {
    asm("mma.sync.aligned.m16n8k16.row.col.f32.f16.f16.f32 "
        "{%0,%1,%2,%3},{%4,%5,%6,%7},{%8,%9},{%10,%11,%12,%13};"
        : "=f"(d[0]), "=f"(d[1]), "=f"(d[2]), "=f"(d[3])
        : "r"(a[0]), "r"(a[1]), "r"(a[2]), "r"(a[3]),
          "r"(b0), "r"(b1),
          "f"(c[0]), "f"(c[1]), "f"(c[2]), "f"(c[3]));
}
__device__ __forceinline__ void ldsm4(uint32_t* r, uint32_t a) {
    asm volatile("ldmatrix.sync.aligned.m8n8.x4.shared.b16 {%0,%1,%2,%3}, [%4];"
        : "=r"(r[0]), "=r"(r[1]), "=r"(r[2]), "=r"(r[3]) : "r"(a));
}
__device__ __forceinline__ void ldsm4t(uint32_t* r, uint32_t a) {
    asm volatile("ldmatrix.sync.aligned.m8n8.x4.trans.shared.b16 {%0,%1,%2,%3}, [%4];"
        : "=r"(r[0]), "=r"(r[1]), "=r"(r[2]), "=r"(r[3]) : "r"(a));
}
__device__ __forceinline__ uint32_t smem_u32(const void* p) {
    uint32_t a;
    asm("{ .reg .u64 t; cvta.to.shared.u64 t, %1; cvt.u32.u64 %0, t; }" : "=r"(a) : "l"(p));
    return a;
}
// .cg: bypass L1 on the global->smem fill (no L1 reuse on streamed operands)
__device__ __forceinline__ void cpa16(uint32_t dst_smem, const void* src) {
    asm volatile("cp.async.cg.shared.global [%0], [%1], 16;" :: "r"(dst_smem), "l"(src));
}
__device__ __forceinline__ void cpa_commit() { asm volatile("cp.async.commit_group;"); }
template<int N> __device__ __forceinline__ void cpa_wait() {
    asm volatile("cp.async.wait_group %0;" :: "n"(N));
}

// fp16 tile: rows of 128B (64 halfs), 8 chunks of 16B, chunk c of row r at c^(r&7)
#define TOFF(row, ch) (((row) << 7) + (((ch) ^ ((row) & 7)) << 4))
// f32 bias tile: rows of 256B (64 floats), 16 chunks of 16B
#define BOFF(row, ch) (((row) << 8) + (((ch) ^ (((row) & 7) << 1)) << 4))

// ---------------- fp16 pre-conversion: all three tensors in one launch --------------
__global__ void cvt_all(const float4* __restrict__ x,
                        const float4* __restrict__ wi,
                        const float4* __restrict__ wo)
{
    const int total = N4X + N4WI + N4WO;
    for (int i = blockIdx.x * blockDim.x + threadIdx.x; i < total;
         i += gridDim.x * blockDim.x) {
        const float4* src; int j; int off;
        if (i < N4X)              { src = x;  j = i;               off = XH; }
        else if (i < N4X + N4WI)  { src = wi; j = i - N4X;         off = WIH; }
        else                      { src = wo; j = i - N4X - N4WI;  off = WOH; }
        float4 v = src[j];
        __half2* out = (__half2*)(g_h + off);
        out[2 * j]     = __floats2half2_rn(v.x, v.y);
        out[2 * j + 1] = __floats2half2_rn(v.z, v.w);
    }
}

// ---------------- mask dtype detection + float materialization ----------------
__global__ void mask_prep(const void* __restrict__ raw, int n)
{
    __shared__ int notint, notfloat;
    if (threadIdx.x == 0) { notint = 0; notfloat = 0; }
    __syncthreads();
    const unsigned* w = (const unsigned*)raw;
    const float*    f = (const float*)raw;
    int nw = n >> 2;
    for (int i = threadIdx.x; i < nw; i += blockDim.x) {
        unsigned x = w[i];
        if (x > 1u) notint = 1;
        float xf = f[i];
        if (xf != 0.0f && xf != 1.0f) notfloat = 1;
    }
    __syncthreads();
    const float MV = LNEG * LOG2E;
    if (!notint) {
        const int* wi = (const int*)raw;
        for (int i = threadIdx.x; i < n; i += blockDim.x)
            g_maskf[i] = wi[i] ? MV : 0.0f;
    } else if (!notfloat) {
        for (int i = threadIdx.x; i < n; i += blockDim.x)
            g_maskf[i] = (f[i] != 0.0f) ? MV : 0.0f;
    } else {
        const unsigned char* c = (const unsigned char*)raw;
        for (int i = threadIdx.x; i < n; i += blockDim.x)
            g_maskf[i] = c[i] ? MV : 0.0f;
    }
}

// ---------------- fp16 NT GEMM: 128x128 tile, k-slab 64, 3-stage cp.async -----------
// MODE 1: A = x (g_h+XH), B = W_in (g_h+WIH) -> scatter q/k/v fp16 [part][b][h][l][d]
// MODE 0: A = g_aoh,      B = W_out (g_h+WOH) -> C row-major fp32 (+bias)
#define STG 3
template<int MODE>
__global__ __launch_bounds__(256, 2) void hgemm(
    const float* __restrict__ bias, float* __restrict__ C, int N)
{
    extern __shared__ char smem[];
    const uint32_t sb = smem_u32(smem);

    const int tid = threadIdx.x;
    const int lane = tid & 31, wid = tid >> 5;
    const int gid = lane >> 2, tig = lane & 3;
    const int sub = lane >> 3, lr = lane & 7;
    const int subhi = sub >> 1, sublo = sub & 1;
    const int wm = wid & 1, wn = wid >> 1;
    const int m0 = blockIdx.y * 128, n0 = blockIdx.x * 128;

    const __half* Ap = (MODE == 0) ? g_aoh : (g_h + XH);
    const __half* Bw = (MODE == 0) ? (g_h + WOH) : (g_h + WIH);
    const int K = D_;

    float acc[4][4][4];
    #pragma unroll
    for (int mt = 0; mt < 4; mt++)
        #pragma unroll
        for (int nt = 0; nt < 4; nt++)
            #pragma unroll
            for (int c = 0; c < 4; c++) acc[mt][nt][c] = 0.0f;

    auto stage = [&](int t, int s) {
        uint32_t base = sb + s * 32768;
        #pragma unroll
        for (int p = 0; p < 8; p++) {
            int idx = tid + 256 * p;
            int mat = idx >> 10;
            int rc  = idx & 1023;
            int row = rc >> 3, ch = rc & 7;
            const __half* src = (mat ? Bw + (size_t)(n0 + row) * K
                                     : Ap + (size_t)(m0 + row) * K) + t * 64 + ch * 8;
            cpa16(base + mat * 16384 + TOFF(row, ch), src);
        }
        cpa_commit();
    };

    stage(0, 0);
    stage(1, 1);
    stage(2, 2);

    const int T = K / 64;
    for (int t = 0; t < T; t++) {
        cpa_wait<STG - 1>();
        __syncthreads();
        uint32_t Ab = sb + (t % STG) * 32768;
        uint32_t Bb = Ab + 16384;

        #pragma unroll
        for (int kk = 0; kk < 4; kk++) {
            int ch = 2 * kk + subhi;
            uint32_t afr[4][4], bfr[2][4];
            #pragma unroll
            for (int mt = 0; mt < 4; mt++) {
                int row = wm * 64 + mt * 16 + sublo * 8 + lr;
                ldsm4(afr[mt], Ab + ((row << 7) + ((ch ^ lr) << 4)));
            }
            #pragma unroll
            for (int ng = 0; ng < 2; ng++) {
                int row = wn * 32 + ng * 16 + sublo * 8 + lr;
                ldsm4(bfr[ng], Bb + ((row << 7) + ((ch ^ lr) << 4)));
            }
            #pragma unroll
            for (int mt = 0; mt < 4; mt++)
                #pragma unroll
                for (int nt = 0; nt < 4; nt++)
                    mma_f16(acc[mt][nt], afr[mt],
                            bfr[nt >> 1][nt & 1], bfr[nt >> 1][(nt & 1) + 2],
                            acc[mt][nt]);
        }
        __syncthreads();
        if (t + STG < T) stage(t + STG, (t + STG) % STG);
    }

    #pragma unroll
    for (int mt = 0; mt < 4; mt++) {
        #pragma unroll
        for (int hh = 0; hh < 2; hh++) {
            int m = m0 + wm * 64 + mt * 16 + gid + hh * 8;
            #pragma unroll
            for (int nt = 0; nt < 4; nt++) {
                int n = n0 + wn * 32 + nt * 8 + 2 * tig;
                float vx = acc[mt][nt][2 * hh]     + bias[n];
                float vy = acc[mt][nt][2 * hh + 1] + bias[n + 1];
                if (MODE == 0) {
                    float2 val = { vx, vy };
                    *(float2*)&C[(size_t)m * N + n] = val;
                } else {
                    int part = n >> 10;
                    int col  = n & 1023;
                    int hd   = col >> 6;
                    int dd   = col & 63;
                    int bb   = m >> 11;
                    int ll   = m & 2047;
                    *(__half2*)&g_qkvh[((((size_t)part * B_ + bb) * H_ + hd) * L_ + ll) * HD + dd] =
                        __floats2half2_rn(vx, vy);
                }
            }
        }
    }
}

// ---------------- flash attention: fused softmax+PV per k-slice, reg P, dbuf K/V ----
// 128 threads = 4 warps; warp w owns q rows [w*16, w*16+16).
// smem: K/V buf0 16KB | K/V buf1 16KB | bias f32 16KB | Q 8KB = 56KB -> occ 4
__global__ __launch_bounds__(128, 4) void flash_h(const float* __restrict__ attn_bias)
{
    extern __shared__ char smf[];
    const uint32_t sb = smem_u32(smf);      // K/V bufs: s*16384 (K +0, V +8192)
    const uint32_t sB = sb + 32768;         // bias: 64 rows x 256B
    const uint32_t sQ = sb + 49152;         // Q: 64 rows x 128B
    const char*    Bf = smf + 32768;

    const int tid = threadIdx.x;
    const int lane = tid & 31, w = tid >> 5;
    const int gid = lane >> 2, tig = lane & 3;
    const int sub = lane >> 3, lr = lane & 7;
    const int subhi = sub >> 1, sublo = sub & 1;
    const int b = blockIdx.z, h = blockIdx.y, q0 = blockIdx.x * 64;

    const __half* Qg = g_qkvh + (((size_t)(0 * B_ + b) * H_ + h) * L_ + q0) * HD;
    const __half* Kg = g_qkvh + (((size_t)(1 * B_ + b) * H_ + h) * L_) * HD;
    const __half* Vg = g_qkvh + (((size_t)(2 * B_ + b) * H_ + h) * L_) * HD;
    const float* biasbase = attn_bias + (((size_t)b * H_ + h) * L_ + q0) * L_;
    const float* mkb = g_maskf + b * L_;

    // K/V stager (all threads): 2 mats x 64 rows x 8 chunks = 1024 over 128 threads
    auto stageA = [&](int t, int s) {
        uint32_t base = sb + s * 16384;
        #pragma unroll
        for (int p = 0; p < 8; p++) {
            int idx = tid + 128 * p;
            int mat = idx >> 9;
            int rc  = idx & 511;
            int row = rc >> 3, ch = rc & 7;
            const __half* src = (mat ? Vg : Kg) + (size_t)(t * 64 + row) * HD + ch * 8;
            cpa16(base + mat * 8192 + TOFF(row, ch), src);
        }
        cpa_commit();
    };
    // bias stager, WARP-LOCAL rows [16w,16w+16): 16 rows x 16 chunks over 32 lanes
    auto stageB = [&](int t) {
        #pragma unroll
        for (int p = 0; p < 8; p++) {
            int idx = lane + 32 * p;          // 0..255
            int row = w * 16 + (idx >> 4);
            int ch  = idx & 15;
            cpa16(sB + BOFF(row, ch), biasbase + (size_t)row * L_ + t * 64 + ch * 4);
        }
        cpa_commit();
    };

    // stage Q, pull persistent A-fragments
    #pragma unroll
    for (int p = 0; p < 4; p++) {
        int idx = tid + 128 * p;
        int row = idx >> 3, ch = idx & 7;
        cpa16(sQ + TOFF(row, ch), Qg + row * HD + ch * 8);
    }
    cpa_commit(); cpa_wait<0>();
    __syncthreads();

    uint32_t aq[4][4];
    {
        int row = w * 16 + sublo * 8 + lr;
        #pragma unroll
        for (int kk = 0; kk < 4; kk++)
            ldsm4(aq[kk], sQ + ((row << 7) + (((2 * kk + subhi) ^ lr) << 4)));
    }

    float o[8][4];
    #pragma unroll
    for (int nt = 0; nt < 8; nt++)
        #pragma unroll
        for (int c = 0; c < 4; c++) o[nt][c] = 0.0f;
    float den[2] = { 0.0f, 0.0f };

    const float SC = 0.125f * LOG2E;

    stageA(0, 0);
    stageB(0);

    const int T = L_ / 64;   // 32 key tiles
    for (int t = 0; t < T; t++) {
        const int k0 = t * 64;
        // per-thread group order: ..., A_t, B_t  ->  wait all but newest 1 => A_t done
        cpa_wait<1>();
        __syncthreads();               // all warps past tile t-1; A_t visible to all
        if (t + 1 < T) stageA(t + 1, (t + 1) & 1);   // pending: B_t, A_{t+1}

        float2 mkv[8];
        #pragma unroll
        for (int nt = 0; nt < 8; nt++)
            mkv[nt] = *(const float2*)(mkb + k0 + nt * 8 + 2 * tig);

        const uint32_t sK = sb + (t & 1) * 16384;
        const uint32_t sV = sK + 8192;

        // S = Q K^T
        float s[8][4];
        #pragma unroll
        for (int nt = 0; nt < 8; nt++)
            #pragma unroll
            for (int c = 0; c < 4; c++) s[nt][c] = 0.0f;
        #pragma unroll
        for (int kk = 0; kk < 4; kk++) {
            int ch = 2 * kk + subhi;
            uint32_t bfr[4][4];
            #pragma unroll
            for (int ng = 0; ng < 4; ng++) {
                int row = ng * 16 + sublo * 8 + lr;
                ldsm4(bfr[ng], sK + ((row << 7) + ((ch ^ lr) << 4)));
            }
            #pragma unroll
            for (int nt = 0; nt < 8; nt++)
                mma_f16(s[nt], aq[kk],
                        bfr[nt >> 1][nt & 1], bfr[nt >> 1][(nt & 1) + 2],
                        s[nt]);
        }

        // bias B_t ready: all but newest (A_{t+1}) done; warp-local rows
        if (t + 1 < T) cpa_wait<1>(); else cpa_wait<0>();
        __syncwarp();

        // fold bias+mask into s (frees the bias buffer fast)
        #pragma unroll
        for (int hh = 0; hh < 2; hh++) {
            int r = w * 16 + gid + 8 * hh;
            #pragma unroll
            for (int nt = 0; nt < 8; nt++) {
                int chb = 2 * nt + (tig >> 1);
                const float* bp = (const float*)(Bf +
                    ((r << 8) + ((chb ^ ((r & 7) << 1)) << 4) + 8 * (tig & 1)));
                float2 bb = *(const float2*)bp;
                s[nt][2 * hh]     = fmaf(s[nt][2 * hh],     SC, fmaf(bb.x, LOG2E, -mkv[nt].x));
                s[nt][2 * hh + 1] = fmaf(s[nt][2 * hh + 1], SC, fmaf(bb.y, LOG2E, -mkv[nt].y));
            }
        }
        __syncwarp();                   // this warp done reading its bias rows
        if (t + 1 < T) stageB(t + 1);   // refill warp-local bias for t+1 (overlaps below)

        // fused softmax + PV per k-slice: exp just nt=2kk,2kk+1, then 8 PV mma.
        #pragma unroll
        for (int kk = 0; kk < 4; kk++) {
            uint32_t vf[4][4];
            #pragma unroll
            for (int ng = 0; ng < 4; ng++) {
                int row = kk * 16 + sublo * 8 + lr;
                int ch  = 2 * ng + subhi;
                ldsm4t(vf[ng], sV + ((row << 7) + ((ch ^ lr) << 4)));
            }
            uint32_t pa[4];
            #pragma unroll
            for (int half = 0; half < 2; half++) {
                int nt = 2 * kk + half;
                #pragma unroll
                for (int hh = 0; hh < 2; hh++) {
                    float p0 = ex2(s[nt][2 * hh]);
                    float p1 = ex2(s[nt][2 * hh + 1]);
                    den[hh] += p0 + p1;
                    __half2 hp = __floats2half2_rn(p0, p1);
                    pa[hh + 2 * half] = *(uint32_t*)&hp;
                }
            }
            #pragma unroll
            for (int nt = 0; nt < 8; nt++)
                mma_f16(o[nt], pa,
                        vf[nt >> 1][(nt & 1) * 2], vf[nt >> 1][(nt & 1) * 2 + 1],
                        o[nt]);
        }
    }

    // reduce den within lane-quad
    #pragma unroll
    for (int hh = 0; hh < 2; hh++) {
        den[hh] += __shfl_xor_sync(0xffffffffu, den[hh], 1);
        den[hh] += __shfl_xor_sync(0xffffffffu, den[hh], 2);
    }

    // normalize + write fp16 attn-out (feeds MODE0 GEMM)
    #pragma unroll
    for (int hh = 0; hh < 2; hh++) {
        float inv = 1.0f / den[hh];
        int l = q0 + w * 16 + gid + 8 * hh;
        #pragma unroll
        for (int nt = 0; nt < 8; nt++) {
            *(__half2*)&g_aoh[((size_t)b * L_ + l) * D_ + h * HD + nt * 8 + 2 * tig] =
                __floats2half2_rn(o[nt][2 * hh] * inv, o[nt][2 * hh + 1] * inv);
        }
    }
}

// ---------------- launch ----------------
extern "C" void kernel_launch(void* const* d_in, const int* in_sizes, int n_in,
                              void* d_out, int out_size)
{
    const float* x      = (const float*)d_in[0];
    const void*  mask   = d_in[1];
    const float* attn_b = (const float*)d_in[2];
    const float* b_in   = (const float*)d_in[4];
    const float* b_out  = (const float*)d_in[6];
    float*       out    = (float*)d_out;

    (void)in_sizes; (void)n_in; (void)out_size;

    mask_prep<<<1, 256>>>(mask, B_ * L_);
    cvt_all<<<1480, 256>>>((const float4*)x, (const float4*)d_in[3], (const float4*)d_in[5]);

    int gsmem = STG * 32768;   // 98,304 B
    cudaFuncSetAttribute(hgemm<1>, cudaFuncAttributeMaxDynamicSharedMemorySize, gsmem);
    cudaFuncSetAttribute(hgemm<0>, cudaFuncAttributeMaxDynamicSharedMemorySize, gsmem);

    // QKV projection -> q/k/v fp16
    hgemm<1><<<dim3((3 * D_) / 128, (B_ * L_) / 128), 256, gsmem>>>(
        b_in, nullptr, 3 * D_);

    int fsmem = 57344;   // 56 KB -> 4 CTAs/SM
    cudaFuncSetAttribute(flash_h, cudaFuncAttributeMaxDynamicSharedMemorySize, fsmem);
    flash_h<<<dim3(L_ / 64, H_, B_), 128, fsmem>>>(attn_b);

    // Output projection -> fp32 out
    hgemm<0><<<dim3(D_ / 128, (B_ * L_) / 128), 256, gsmem>>>(
        b_out, out, D_);
}